// round 9
// baseline (speedup 1.0000x reference)
#include <cuda_runtime.h>
#include <cstdint>

// Problem constants
#define T_STEPS   32768
#define RDIM      1024
#define IN_DIM    128
#define OUT_DIM   64

// Scan config: 64 persistent blocks, 512 threads, 16 rows of W per block,
// per-thread tile = 4 rows x 8 cols (32 fp32 weights in registers).
#define GBLK      64
#define TPB       512
#define RPB       16          // rows per block (1024/64)
#define CHUNK     16          // state floats per block (1024/64)

// ---------------- static device scratch (no allocations allowed) -------------
__device__ float g_u[(size_t)T_STEPS * RDIM];             // 128 MB  u[t][r]
__device__ float g_states[(size_t)(T_STEPS + 1) * RDIM];  // 128 MB  row 0 = s_{-1}=0, row t+1 = s_t
__device__ int   g_flags[GBLK];                           // flag[b] = #steps completed by block b

// ---------------- init: zero flags + first state row ------------------------
__global__ void k_init() {
    int tid = threadIdx.x;  // 256 threads
    if (tid < GBLK) g_flags[tid] = 0;
#pragma unroll
    for (int i = 0; i < 4; i++) g_states[tid * 4 + i] = 0.0f;
}

// ---------------- accurate tanh (err ~1e-7, no overflow) --------------------
__device__ __forceinline__ float tanh_acc(float x) {
    float ax = fabsf(x);
    // e^{-2|x|} = 2^{-2|x|*log2(e)}
    float z = exp2f(-2.8853900817779268f * ax);
    float t = __fdividef(1.0f - z, 1.0f + z);
    return copysignf(t, x);
}

// =============================================================================
// Kernel 1: u[t][r] = sum_k input[t][k] * Win[r][k]   (NT GEMM, 64x64 tiles)
// =============================================================================
__global__ __launch_bounds__(256) void k_u(const float* __restrict__ inp,
                                           const float* __restrict__ win) {
    __shared__ float As[64][68];  // As[k][t]
    __shared__ float Bs[64][68];  // Bs[k][r]
    const int t0 = blockIdx.x * 64;
    const int r0 = blockIdx.y * 64;
    const int tid = threadIdx.x;
    const int tx = tid & 15, ty = tid >> 4;

    float acc[4][4];
#pragma unroll
    for (int i = 0; i < 4; i++)
#pragma unroll
        for (int j = 0; j < 4; j++) acc[i][j] = 0.0f;

#pragma unroll
    for (int kc = 0; kc < IN_DIM; kc += 64) {
#pragma unroll
        for (int it = 0; it < 4; it++) {
            int idx = tid + it * 256;          // 0..1023 (float4 slots)
            int tt = idx >> 4;                 // 0..63
            int k4 = idx & 15;                 // 0..15
            float4 va = *(const float4*)(inp + (size_t)(t0 + tt) * IN_DIM + kc + k4 * 4);
            As[k4 * 4 + 0][tt] = va.x; As[k4 * 4 + 1][tt] = va.y;
            As[k4 * 4 + 2][tt] = va.z; As[k4 * 4 + 3][tt] = va.w;
            float4 vb = *(const float4*)(win + (size_t)(r0 + tt) * IN_DIM + kc + k4 * 4);
            Bs[k4 * 4 + 0][tt] = vb.x; Bs[k4 * 4 + 1][tt] = vb.y;
            Bs[k4 * 4 + 2][tt] = vb.z; Bs[k4 * 4 + 3][tt] = vb.w;
        }
        __syncthreads();
#pragma unroll
        for (int k = 0; k < 64; k++) {
            float4 a = *(const float4*)&As[k][ty * 4];
            float4 b = *(const float4*)&Bs[k][tx * 4];
            float av[4] = {a.x, a.y, a.z, a.w};
            float bv[4] = {b.x, b.y, b.z, b.w};
#pragma unroll
            for (int i = 0; i < 4; i++)
#pragma unroll
                for (int j = 0; j < 4; j++) acc[i][j] = fmaf(av[i], bv[j], acc[i][j]);
        }
        __syncthreads();
    }
#pragma unroll
    for (int i = 0; i < 4; i++) {
        float4 o = make_float4(acc[i][0], acc[i][1], acc[i][2], acc[i][3]);
        *(float4*)(g_u + (size_t)(t0 + ty * 4 + i) * RDIM + r0 + tx * 4) = o;
    }
}

// =============================================================================
// Kernel 2: the sequential scan. 64 persistent blocks, W slice in registers,
// fine-grained flag dataflow through L2.
// =============================================================================
__global__ __launch_bounds__(TPB, 1) void k_scan(const float* __restrict__ W) {
    const int b   = blockIdx.x;
    const int tid = threadIdx.x;
    const int w   = tid >> 5;        // warp 0..15
    const int l   = tid & 31;
    const int g   = w >> 2;          // row group 0..3 (4 rows each)
    const int q   = w & 3;           // col quadrant (256 cols each)
    const int rowbase = b * RPB + g * 4;
    const int cbase   = q * 256 + l * 8;
    const int myflag  = cbase >> 4;  // chunk index this thread consumes

    // Load my 4x8 weight tile into registers (stays for the whole scan)
    float4 wv[4][2];
#pragma unroll
    for (int i = 0; i < 4; i++) {
        const float4* p = (const float4*)(W + (size_t)(rowbase + i) * RDIM + cbase);
        wv[i][0] = p[0];
        wv[i][1] = p[1];
    }

    __shared__ float4 part4[2][16];  // [t&1][warp] : 4 row-partials per warp

    const bool isOut = (w == 0 && l < 16);
    const int outrow = b * RPB + l;  // valid when isOut
    float s_my = 0.0f;               // previous state of my output row

    for (int t = 0; t < T_STEPS; t++) {
        // prefetch u[t][outrow] early (latency hides under poll+compute)
        float uval = 0.0f;
        if (isOut) uval = __ldg(&g_u[(size_t)t * RDIM + outrow]);

        // wait for my state chunk of step t-1 (flags[j] >= t). t=0 passes (flags=0).
        {
            const int* fp = g_flags + myflag;
            int f;
            do {
                asm volatile("ld.acquire.gpu.b32 %0, [%1];" : "=r"(f) : "l"(fp) : "memory");
            } while (f < t);
        }

        // load s_{t-1}[cbase..cbase+7]  (row t of g_states; row 0 is zeros)
        const float4* sp = (const float4*)(g_states + (size_t)t * RDIM + cbase);
        float4 s0 = sp[0], s1 = sp[1];

        // 32 FMAs: partial dot for 4 rows over 8 cols
        float a0 = wv[0][0].x*s0.x + wv[0][0].y*s0.y + wv[0][0].z*s0.z + wv[0][0].w*s0.w
                 + wv[0][1].x*s1.x + wv[0][1].y*s1.y + wv[0][1].z*s1.z + wv[0][1].w*s1.w;
        float a1 = wv[1][0].x*s0.x + wv[1][0].y*s0.y + wv[1][0].z*s0.z + wv[1][0].w*s0.w
                 + wv[1][1].x*s1.x + wv[1][1].y*s1.y + wv[1][1].z*s1.z + wv[1][1].w*s1.w;
        float a2 = wv[2][0].x*s0.x + wv[2][0].y*s0.y + wv[2][0].z*s0.z + wv[2][0].w*s0.w
                 + wv[2][1].x*s1.x + wv[2][1].y*s1.y + wv[2][1].z*s1.z + wv[2][1].w*s1.w;
        float a3 = wv[3][0].x*s0.x + wv[3][0].y*s0.y + wv[3][0].z*s0.z + wv[3][0].w*s0.w
                 + wv[3][1].x*s1.x + wv[3][1].y*s1.y + wv[3][1].z*s1.z + wv[3][1].w*s1.w;

        // butterfly reduce over 32 lanes (256 cols per warp)
#pragma unroll
        for (int off = 16; off > 0; off >>= 1) {
            a0 += __shfl_xor_sync(0xFFFFFFFFu, a0, off);
            a1 += __shfl_xor_sync(0xFFFFFFFFu, a1, off);
            a2 += __shfl_xor_sync(0xFFFFFFFFu, a2, off);
            a3 += __shfl_xor_sync(0xFFFFFFFFu, a3, off);
        }
        if (l == 0) part4[t & 1][w] = make_float4(a0, a1, a2, a3);
        __syncthreads();

        // warp 0 lanes 0..15: combine 4 quadrants, tanh, write chunk + flag
        if (isOut) {
            const float* pf = (const float*)&part4[t & 1][0];
            int gg = l >> 2, ii = l & 3;
            float d = pf[(gg * 4 + 0) * 4 + ii] + pf[(gg * 4 + 1) * 4 + ii]
                    + pf[(gg * 4 + 2) * 4 + ii] + pf[(gg * 4 + 3) * 4 + ii];
            // s_new = 0.5*s_prev + 0.5*tanh(u + 0.5*(W s_prev))
            float snew = 0.5f * s_my + 0.5f * tanh_acc(fmaf(0.5f, d, uval));
            s_my = snew;
            g_states[(size_t)(t + 1) * RDIM + outrow] = snew;
            __threadfence();
            __syncwarp(0x0000FFFFu);
            if (l == 0) {
                int v = t + 1;
                asm volatile("st.release.gpu.b32 [%0], %1;"
                             :: "l"(g_flags + b), "r"(v) : "memory");
            }
        }
        // other warps proceed immediately to next step's poll (part ping-pong:
        // overwrite of part[t&1] at t+2 is ordered after warp0's reads via the
        // release->acquire flag chain through all 64 blocks).
    }
}

// =============================================================================
// Kernel 3: predictions[t][o] = sum_r states_t[r] * Wout[r][o]
// (states_t = g_states row t+1; Wout is [1024][64] row-major = already [k][o])
// =============================================================================
__global__ __launch_bounds__(256) void k_out(const float* __restrict__ wout,
                                             float* __restrict__ pred) {
    __shared__ float As[64][68];  // As[k][t]
    __shared__ float Bs[64][68];  // Bs[k][o]
    const int t0 = blockIdx.x * 64;
    const int tid = threadIdx.x;
    const int tx = tid & 15, ty = tid >> 4;

    float acc[4][4];
#pragma unroll
    for (int i = 0; i < 4; i++)
#pragma unroll
        for (int j = 0; j < 4; j++) acc[i][j] = 0.0f;

    for (int kc = 0; kc < RDIM; kc += 64) {
#pragma unroll
        for (int it = 0; it < 4; it++) {
            int idx = tid + it * 256;
            int tt = idx >> 4;
            int k4 = idx & 15;
            float4 va = *(const float4*)(g_states + (size_t)(t0 + tt + 1) * RDIM + kc + k4 * 4);
            As[k4 * 4 + 0][tt] = va.x; As[k4 * 4 + 1][tt] = va.y;
            As[k4 * 4 + 2][tt] = va.z; As[k4 * 4 + 3][tt] = va.w;
            // B: rows kk of wout chunk, direct copy (already [k][o])
            int kk = idx >> 4;
            int o4 = idx & 15;
            float4 vb = *(const float4*)(wout + (size_t)(kc + kk) * OUT_DIM + o4 * 4);
            *(float4*)&Bs[kk][o4 * 4] = vb;
        }
        __syncthreads();
#pragma unroll
        for (int k = 0; k < 64; k++) {
            float4 a = *(const float4*)&As[k][ty * 4];
            float4 b = *(const float4*)&Bs[k][tx * 4];
            float av[4] = {a.x, a.y, a.z, a.w};
            float bv[4] = {b.x, b.y, b.z, b.w};
#pragma unroll
            for (int i = 0; i < 4; i++)
#pragma unroll
                for (int j = 0; j < 4; j++) acc[i][j] = fmaf(av[i], bv[j], acc[i][j]);
        }
        __syncthreads();
    }
#pragma unroll
    for (int i = 0; i < 4; i++) {
        float4 o = make_float4(acc[i][0], acc[i][1], acc[i][2], acc[i][3]);
        *(float4*)(pred + (size_t)(t0 + ty * 4 + i) * OUT_DIM + tx * 4) = o;
    }
}

// =============================================================================
extern "C" void kernel_launch(void* const* d_in, const int* in_sizes, int n_in,
                              void* d_out, int out_size) {
    // Identify inputs robustly by element count (all four sizes are distinct).
    const float* inp  = nullptr;  // 32768*128
    const float* win  = nullptr;  // 1024*128
    const float* W    = nullptr;  // 1024*1024
    const float* wout = nullptr;  // 1024*64
    for (int i = 0; i < n_in; i++) {
        switch (in_sizes[i]) {
            case T_STEPS * IN_DIM:   inp  = (const float*)d_in[i]; break;
            case RDIM * IN_DIM:      win  = (const float*)d_in[i]; break;
            case RDIM * RDIM:        W    = (const float*)d_in[i]; break;
            case RDIM * OUT_DIM:     wout = (const float*)d_in[i]; break;
            default: break;
        }
    }
    // Fallback to declared order if sizes ever collide.
    if (!inp)  inp  = (const float*)d_in[0];
    if (!win)  win  = (const float*)d_in[1];
    if (!W)    W    = (const float*)d_in[2];
    if (!wout) wout = (const float*)d_in[3];

    k_init<<<1, 256>>>();
    k_u<<<dim3(T_STEPS / 64, RDIM / 64), 256>>>(inp, win);
    k_scan<<<GBLK, TPB>>>(W);
    k_out<<<T_STEPS / 64, 256>>>(wout, (float*)d_out);
}

// round 10
// speedup vs baseline: 3.3611x; 3.3611x over previous
#include <cuda_runtime.h>
#include <cstdint>

// Problem constants
#define T_STEPS   32768
#define RDIM      1024
#define IN_DIM    128
#define OUT_DIM   64

// Scan config: 64 persistent blocks, 512 threads, 16 rows of W per block,
// per-thread tile = 4 rows x 8 cols (32 fp32 weights in registers).
#define GBLK      64
#define TPB       512
#define RPB       16          // rows per block (1024/64)

// ---------------- static device scratch (no allocations allowed) -------------
__device__ float g_u[(size_t)T_STEPS * RDIM];             // 128 MB  u[t][r]
__device__ float g_states[(size_t)(T_STEPS + 1) * RDIM];  // 128 MB  row 0 = s_{-1}=0, row t+1 = s_t
__device__ int   g_flags[GBLK];                           // flag[b] = #steps completed by block b

// ---------------- init: zero flags + first state row ------------------------
__global__ void k_init() {
    int tid = threadIdx.x;  // 256 threads
    if (tid < GBLK) g_flags[tid] = 0;
#pragma unroll
    for (int i = 0; i < 4; i++) g_states[tid * 4 + i] = 0.0f;
}

// ---------------- accurate tanh (err ~1e-7, no overflow) --------------------
__device__ __forceinline__ float tanh_acc(float x) {
    float ax = fabsf(x);
    // e^{-2|x|} = 2^{-2|x|*log2(e)}
    float z = exp2f(-2.8853900817779268f * ax);
    float t = __fdividef(1.0f - z, 1.0f + z);
    return copysignf(t, x);
}

// =============================================================================
// Kernel 1: u[t][r] = sum_k input[t][k] * Win[r][k]   (NT GEMM, 64x64 tiles)
// =============================================================================
__global__ __launch_bounds__(256) void k_u(const float* __restrict__ inp,
                                           const float* __restrict__ win) {
    __shared__ float As[64][68];  // As[k][t]
    __shared__ float Bs[64][68];  // Bs[k][r]
    const int t0 = blockIdx.x * 64;
    const int r0 = blockIdx.y * 64;
    const int tid = threadIdx.x;
    const int tx = tid & 15, ty = tid >> 4;

    float acc[4][4];
#pragma unroll
    for (int i = 0; i < 4; i++)
#pragma unroll
        for (int j = 0; j < 4; j++) acc[i][j] = 0.0f;

#pragma unroll
    for (int kc = 0; kc < IN_DIM; kc += 64) {
#pragma unroll
        for (int it = 0; it < 4; it++) {
            int idx = tid + it * 256;          // 0..1023 (float4 slots)
            int tt = idx >> 4;                 // 0..63
            int k4 = idx & 15;                 // 0..15
            float4 va = *(const float4*)(inp + (size_t)(t0 + tt) * IN_DIM + kc + k4 * 4);
            As[k4 * 4 + 0][tt] = va.x; As[k4 * 4 + 1][tt] = va.y;
            As[k4 * 4 + 2][tt] = va.z; As[k4 * 4 + 3][tt] = va.w;
            float4 vb = *(const float4*)(win + (size_t)(r0 + tt) * IN_DIM + kc + k4 * 4);
            Bs[k4 * 4 + 0][tt] = vb.x; Bs[k4 * 4 + 1][tt] = vb.y;
            Bs[k4 * 4 + 2][tt] = vb.z; Bs[k4 * 4 + 3][tt] = vb.w;
        }
        __syncthreads();
#pragma unroll
        for (int k = 0; k < 64; k++) {
            float4 a = *(const float4*)&As[k][ty * 4];
            float4 b = *(const float4*)&Bs[k][tx * 4];
            float av[4] = {a.x, a.y, a.z, a.w};
            float bv[4] = {b.x, b.y, b.z, b.w};
#pragma unroll
            for (int i = 0; i < 4; i++)
#pragma unroll
                for (int j = 0; j < 4; j++) acc[i][j] = fmaf(av[i], bv[j], acc[i][j]);
        }
        __syncthreads();
    }
#pragma unroll
    for (int i = 0; i < 4; i++) {
        float4 o = make_float4(acc[i][0], acc[i][1], acc[i][2], acc[i][3]);
        *(float4*)(g_u + (size_t)(t0 + ty * 4 + i) * RDIM + r0 + tx * 4) = o;
    }
}

// =============================================================================
// Kernel 2: the sequential scan. 64 persistent blocks, W slice in registers.
// R9 changes vs R8:
//   - only 64 dedicated poller threads per block (tid<64), then __syncthreads,
//     instead of all 512 threads spinning (which saturated the flag L2 slices)
//   - flag release via st.release.gpu alone (no redundant __threadfence)
// =============================================================================
__global__ __launch_bounds__(TPB, 1) void k_scan(const float* __restrict__ W) {
    const int b   = blockIdx.x;
    const int tid = threadIdx.x;
    const int w   = tid >> 5;        // warp 0..15
    const int l   = tid & 31;
    const int g   = w >> 2;          // row group 0..3 (4 rows each)
    const int q   = w & 3;           // col quadrant (256 cols each)
    const int rowbase = b * RPB + g * 4;
    const int cbase   = q * 256 + l * 8;

    // Load my 4x8 weight tile into registers (stays for the whole scan)
    float4 wv[4][2];
#pragma unroll
    for (int i = 0; i < 4; i++) {
        const float4* p = (const float4*)(W + (size_t)(rowbase + i) * RDIM + cbase);
        wv[i][0] = p[0];
        wv[i][1] = p[1];
    }

    __shared__ float4 part4[2][16];  // [t&1][warp] : 4 row-partials per warp

    const bool isOut = (w == 0 && l < 16);
    const int outrow = b * RPB + l;  // valid when isOut
    float s_my = 0.0f;               // previous state of my output row

    for (int t = 0; t < T_STEPS; t++) {
        // prefetch u[t][outrow] early (latency hides under poll+compute)
        float uval = 0.0f;
        if (isOut) uval = __ldg(&g_u[(size_t)t * RDIM + outrow]);

        // Dedicated pollers: thread j (<64) waits for block j's flag >= t.
        // t=0 passes immediately (flags zeroed by k_init).
        if (tid < GBLK) {
            const int* fp = g_flags + tid;
            int f;
            do {
                asm volatile("ld.acquire.gpu.b32 %0, [%1];" : "=r"(f) : "l"(fp) : "memory");
            } while (f < t);
        }
        __syncthreads();   // acquire by pollers + cta barrier orders the loads below

        // load s_{t-1}[cbase..cbase+7]  (row t of g_states; row 0 is zeros)
        const float4* sp = (const float4*)(g_states + (size_t)t * RDIM + cbase);
        float4 s0 = sp[0], s1 = sp[1];

        // 32 FMAs: partial dot for 4 rows over 8 cols
        float a0 = wv[0][0].x*s0.x + wv[0][0].y*s0.y + wv[0][0].z*s0.z + wv[0][0].w*s0.w
                 + wv[0][1].x*s1.x + wv[0][1].y*s1.y + wv[0][1].z*s1.z + wv[0][1].w*s1.w;
        float a1 = wv[1][0].x*s0.x + wv[1][0].y*s0.y + wv[1][0].z*s0.z + wv[1][0].w*s0.w
                 + wv[1][1].x*s1.x + wv[1][1].y*s1.y + wv[1][1].z*s1.z + wv[1][1].w*s1.w;
        float a2 = wv[2][0].x*s0.x + wv[2][0].y*s0.y + wv[2][0].z*s0.z + wv[2][0].w*s0.w
                 + wv[2][1].x*s1.x + wv[2][1].y*s1.y + wv[2][1].z*s1.z + wv[2][1].w*s1.w;
        float a3 = wv[3][0].x*s0.x + wv[3][0].y*s0.y + wv[3][0].z*s0.z + wv[3][0].w*s0.w
                 + wv[3][1].x*s1.x + wv[3][1].y*s1.y + wv[3][1].z*s1.z + wv[3][1].w*s1.w;

        // butterfly reduce over 32 lanes (256 cols per warp)
#pragma unroll
        for (int off = 16; off > 0; off >>= 1) {
            a0 += __shfl_xor_sync(0xFFFFFFFFu, a0, off);
            a1 += __shfl_xor_sync(0xFFFFFFFFu, a1, off);
            a2 += __shfl_xor_sync(0xFFFFFFFFu, a2, off);
            a3 += __shfl_xor_sync(0xFFFFFFFFu, a3, off);
        }
        if (l == 0) part4[t & 1][w] = make_float4(a0, a1, a2, a3);
        __syncthreads();

        // warp 0 lanes 0..15: combine 4 quadrants, tanh, write chunk + flag
        if (isOut) {
            const float* pf = (const float*)&part4[t & 1][0];
            int gg = l >> 2, ii = l & 3;
            float d = pf[(gg * 4 + 0) * 4 + ii] + pf[(gg * 4 + 1) * 4 + ii]
                    + pf[(gg * 4 + 2) * 4 + ii] + pf[(gg * 4 + 3) * 4 + ii];
            // s_new = 0.5*s_prev + 0.5*tanh(u + 0.5*(W s_prev))
            float snew = 0.5f * s_my + 0.5f * tanh_acc(fmaf(0.5f, d, uval));
            s_my = snew;
            g_states[(size_t)(t + 1) * RDIM + outrow] = snew;
            __syncwarp(0x0000FFFFu);
            if (l == 0) {
                int v = t + 1;
                // release store orders the 16 state stores above before the flag
                asm volatile("st.release.gpu.b32 [%0], %1;"
                             :: "l"(g_flags + b), "r"(v) : "memory");
            }
        }
    }
}

// =============================================================================
// Kernel 3: predictions[t][o] = sum_r states_t[r] * Wout[r][o]
// (states_t = g_states row t+1; Wout is [1024][64] row-major = already [k][o])
// =============================================================================
__global__ __launch_bounds__(256) void k_out(const float* __restrict__ wout,
                                             float* __restrict__ pred) {
    __shared__ float As[64][68];  // As[k][t]
    __shared__ float Bs[64][68];  // Bs[k][o]
    const int t0 = blockIdx.x * 64;
    const int tid = threadIdx.x;
    const int tx = tid & 15, ty = tid >> 4;

    float acc[4][4];
#pragma unroll
    for (int i = 0; i < 4; i++)
#pragma unroll
        for (int j = 0; j < 4; j++) acc[i][j] = 0.0f;

    for (int kc = 0; kc < RDIM; kc += 64) {
#pragma unroll
        for (int it = 0; it < 4; it++) {
            int idx = tid + it * 256;
            int tt = idx >> 4;
            int k4 = idx & 15;
            float4 va = *(const float4*)(g_states + (size_t)(t0 + tt + 1) * RDIM + kc + k4 * 4);
            As[k4 * 4 + 0][tt] = va.x; As[k4 * 4 + 1][tt] = va.y;
            As[k4 * 4 + 2][tt] = va.z; As[k4 * 4 + 3][tt] = va.w;
            // B: rows kk of wout chunk, direct copy (already [k][o])
            int kk = idx >> 4;
            int o4 = idx & 15;
            float4 vb = *(const float4*)(wout + (size_t)(kc + kk) * OUT_DIM + o4 * 4);
            *(float4*)&Bs[kk][o4 * 4] = vb;
        }
        __syncthreads();
#pragma unroll
        for (int k = 0; k < 64; k++) {
            float4 a = *(const float4*)&As[k][ty * 4];
            float4 b = *(const float4*)&Bs[k][tx * 4];
            float av[4] = {a.x, a.y, a.z, a.w};
            float bv[4] = {b.x, b.y, b.z, b.w};
#pragma unroll
            for (int i = 0; i < 4; i++)
#pragma unroll
                for (int j = 0; j < 4; j++) acc[i][j] = fmaf(av[i], bv[j], acc[i][j]);
        }
        __syncthreads();
    }
#pragma unroll
    for (int i = 0; i < 4; i++) {
        float4 o = make_float4(acc[i][0], acc[i][1], acc[i][2], acc[i][3]);
        *(float4*)(pred + (size_t)(t0 + ty * 4 + i) * OUT_DIM + tx * 4) = o;
    }
}

// =============================================================================
extern "C" void kernel_launch(void* const* d_in, const int* in_sizes, int n_in,
                              void* d_out, int out_size) {
    // Identify inputs robustly by element count (all four sizes are distinct).
    const float* inp  = nullptr;  // 32768*128
    const float* win  = nullptr;  // 1024*128
    const float* W    = nullptr;  // 1024*1024
    const float* wout = nullptr;  // 1024*64
    for (int i = 0; i < n_in; i++) {
        switch (in_sizes[i]) {
            case T_STEPS * IN_DIM:   inp  = (const float*)d_in[i]; break;
            case RDIM * IN_DIM:      win  = (const float*)d_in[i]; break;
            case RDIM * RDIM:        W    = (const float*)d_in[i]; break;
            case RDIM * OUT_DIM:     wout = (const float*)d_in[i]; break;
            default: break;
        }
    }
    // Fallback to declared order if sizes ever collide.
    if (!inp)  inp  = (const float*)d_in[0];
    if (!win)  win  = (const float*)d_in[1];
    if (!W)    W    = (const float*)d_in[2];
    if (!wout) wout = (const float*)d_in[3];

    k_init<<<1, 256>>>();
    k_u<<<dim3(T_STEPS / 64, RDIM / 64), 256>>>(inp, win);
    k_scan<<<GBLK, TPB>>>(W);
    k_out<<<T_STEPS / 64, 256>>>(wout, (float*)d_out);
}